// round 4
// baseline (speedup 1.0000x reference)
#include <cuda_runtime.h>
#include <cstddef>

#define N_ROWS 8192
#define N_COLS 8192
#define THREADS 256
#define N_STEPS 100
#define SPG 25              // steps per 64-thread group (4 groups x 25 = 100)
#define NPAIR 12            // 12 packed step-pairs + 1 scalar step = 25
#define EPT (N_COLS / 64)   // elements per thread within a 64-thread group = 128

__global__ __launch_bounds__(THREADS)
void mse_observer_kernel(const float* __restrict__ x, float* __restrict__ out) {
    __shared__ float row_sm[N_COLS];
    __shared__ float invs[N_STEPS];     // 1/scale_i
    __shared__ float s2k[N_STEPS];      // scale_i^2 / 8192
    __shared__ float thr_sm[N_STEPS];   // thres_i
    __shared__ float partial[8][SPG];   // per-warp partial sums
    __shared__ float red_min[8], red_max[8];
    __shared__ float losses[N_STEPS];
    __shared__ float Rsh, rmin_sh, rmax_sh;

    const int row  = blockIdx.x;
    const int tid  = threadIdx.x;
    const int warp = tid >> 5;
    const int lane = tid & 31;
    const float* xr = x + (size_t)row * N_COLS;

    // ---- Phase A: load row to smem, compute row min/max ----
    float mn = 3.0e38f, mx = -3.0e38f;
    const float4* xr4 = (const float4*)xr;
    float4* row4 = (float4*)row_sm;
    #pragma unroll
    for (int k = 0; k < N_COLS / 4 / THREADS; k++) {   // 8 iterations
        float4 v = xr4[tid + k * THREADS];
        row4[tid + k * THREADS] = v;
        mn = fminf(mn, fminf(fminf(v.x, v.y), fminf(v.z, v.w)));
        mx = fmaxf(mx, fmaxf(fmaxf(v.x, v.y), fmaxf(v.z, v.w)));
    }
    #pragma unroll
    for (int o = 16; o; o >>= 1) {
        mn = fminf(mn, __shfl_xor_sync(0xFFFFFFFFu, mn, o));
        mx = fmaxf(mx, __shfl_xor_sync(0xFFFFFFFFu, mx, o));
    }
    if (lane == 0) { red_min[warp] = mn; red_max[warp] = mx; }
    __syncthreads();
    if (tid == 0) {
        float m = red_min[0], M = red_max[0];
        #pragma unroll
        for (int w = 1; w < 8; w++) { m = fminf(m, red_min[w]); M = fmaxf(M, red_max[w]); }
        rmin_sh = m; rmax_sh = M;
        Rsh = fmaxf(fabsf(m), M);   // range_val = max(|min|, max)
    }
    __syncthreads();

    // ---- Phase B: per-step tables ----
    if (tid < N_STEPS) {
        float R = Rsh;
        float thres = __fdiv_rn(R, 100.0f) * (float)(tid + 1);
        float scale = fmaxf(__fdiv_rn(thres, 127.5f), 1.1920928955078125e-07f);
        thr_sm[tid] = thres;
        invs[tid]   = __fdiv_rn(1.0f, scale);
        s2k[tid]    = scale * scale * (1.0f / 8192.0f);
    }
    __syncthreads();

    // ---- Phase C: main compute, packed f32x2 over step-pairs, |x| form.
    // t = x*inv; u = |x|*inv.  round half-even is sign-symmetric, so
    // (t - clamp(round t,-128,127))^2 = (u - min(round u, cb))^2
    // with cb = 127 for x>=0, 128 for x<0 (lower clamp never binds, u>=0).
    // round(u) via magic M=1.5*2^23: rr = fma(u... = M + round(u) exact for
    // u < 2^22; for u >= 128.5 the min-clamp absorbs any magic-round error.
    const int grp  = tid >> 6;
    const int l64  = tid & 63;
    const int base = grp * SPG;
    const float MAGIC = 12582912.0f;                          // 1.5 * 2^23
    const unsigned long long MAGIC2 = 0x4B4000004B400000ULL;  // {M, M}
    const unsigned long long NEG1x2 = 0xBF800000BF800000ULL;  // {-1, -1}
    const float CB_POS = 12583039.0f;   // M + 127
    const float CB_NEG = 12583040.0f;   // M + 128

    unsigned long long ivp[NPAIR], app[NPAIR];
    #pragma unroll
    for (int j = 0; j < NPAIR; j++) {
        float a = invs[base + 2 * j], b = invs[base + 2 * j + 1];
        asm("mov.b64 %0, {%1,%2};" : "=l"(ivp[j]) : "f"(a), "f"(b));
        app[j] = 0ULL;
    }
    float inv_last = invs[base + 24];
    float acc_last = 0.0f;

    #pragma unroll 2
    for (int k = 0; k < EPT; k++) {
        float xv = row_sm[l64 + (k << 6)];
        float ax = fabsf(xv);
        float cb = (xv < 0.0f) ? CB_NEG : CB_POS;   // M + (x<0 ? 128 : 127)
        unsigned long long aa;
        asm("mov.b64 %0, {%1,%1};" : "=l"(aa) : "f"(ax));
        #pragma unroll
        for (int j = 0; j < NPAIR; j++) {
            asm("{\n\t"
                ".reg .f32 n0,n1;\n\t"
                ".reg .b64 rr,nq,dd;\n\t"
                "fma.rn.f32x2 rr, %1, %2, %3;\n\t"   // M + round(u)
                "mov.b64 {n0,n1}, rr;\n\t"
                "min.f32 n0, n0, %5;\n\t"            // min(.., M+cb)
                "min.f32 n1, n1, %5;\n\t"
                "mov.b64 rr, {n0,n1};\n\t"
                "fma.rn.f32x2 nq, rr, %4, %3;\n\t"   // -q  (exact)
                "fma.rn.f32x2 dd, %1, %2, nq;\n\t"   // u - q
                "fma.rn.f32x2 %0, dd, dd, %0;\n\t"   // acc += d*d
                "}"
                : "+l"(app[j])
                : "l"(aa), "l"(ivp[j]), "l"(MAGIC2), "l"(NEG1x2), "f"(cb));
        }
        // scalar leftover step (index base+24), same |x| trick
        float r  = __fmaf_rn(ax, inv_last, MAGIC);
        r = fminf(r, cb);
        float nq = __fmaf_rn(r, -1.0f, MAGIC);       // -q
        float d  = __fmaf_rn(ax, inv_last, nq);
        acc_last = __fmaf_rn(d, d, acc_last);
    }

    // ---- Phase D: deterministic reductions ----
    #pragma unroll
    for (int j = 0; j < NPAIR; j++) {
        float a0, a1;
        asm("mov.b64 {%0,%1}, %2;" : "=f"(a0), "=f"(a1) : "l"(app[j]));
        #pragma unroll
        for (int o = 16; o; o >>= 1) {
            a0 += __shfl_xor_sync(0xFFFFFFFFu, a0, o);
            a1 += __shfl_xor_sync(0xFFFFFFFFu, a1, o);
        }
        if (lane == 0) { partial[warp][2 * j] = a0; partial[warp][2 * j + 1] = a1; }
    }
    {
        float v = acc_last;
        #pragma unroll
        for (int o = 16; o; o >>= 1) v += __shfl_xor_sync(0xFFFFFFFFu, v, o);
        if (lane == 0) partial[warp][24] = v;
    }
    __syncthreads();
    if (tid < N_STEPS) {
        int g = tid / SPG, jj = tid - g * SPG;
        float sum = partial[2 * g][jj] + partial[2 * g + 1][jj];
        losses[tid] = sum * s2k[tid];   // mean((xq-x)^2)
    }
    __syncthreads();

    // ---- Phase E: sequential argmin scan (matches lax.scan semantics) ----
    if (tid == 0) {
        float best = 1.0e9f;
        float bmin = rmin_sh, bmax = rmax_sh;
        for (int j = 0; j < N_STEPS; j++) {
            float L = losses[j];
            if (L < best) { best = L; bmin = -thr_sm[j]; bmax = thr_sm[j]; }
        }
        out[row] = bmin;
        out[N_ROWS + row] = bmax;
    }
}

extern "C" void kernel_launch(void* const* d_in, const int* in_sizes, int n_in,
                              void* d_out, int out_size) {
    const float* x = (const float*)d_in[0];
    float* out = (float*)d_out;
    mse_observer_kernel<<<N_ROWS, THREADS>>>(x, out);
}

// round 5
// speedup vs baseline: 1.0767x; 1.0767x over previous
#include <cuda_runtime.h>
#include <cstddef>

#define N_ROWS 8192
#define N_COLS 8192
#define THREADS 256
#define N_STEPS 100
#define EPT (N_COLS / 64)   // elements per thread within a 64-thread group = 128
#define MAXP 13

__device__ __forceinline__ float shfl_add(float v) {
    #pragma unroll
    for (int o = 16; o; o >>= 1) v += __shfl_xor_sync(0xFFFFFFFFu, v, o);
    return v;
}

// Group of 64 threads handles NP packed step-pairs starting at step `base`.
// u = |x|*inv;  rr = fma(|x|,inv,M) = M + round(u)  (exact; huge u absorbed by clamp)
// rr = min(rr, M+cb), cb = 127 (x>=0) or 128 (x<0); lower clamp never binds (u>=0)
// nq = M - rr = -q  (exact: same-exponent integers)
// dd = fma(|x|,inv,nq) = u - q;  acc += dd*dd   (rounding identical to R2/R3 kernels)
template<int NP>
__device__ __forceinline__ void run_group(
    const float* __restrict__ row_sm, const float* __restrict__ invs,
    float (*partial)[2 * MAXP], int base, int l64, int warp, int lane,
    unsigned long long M2)
{
    const float CB_POS = 12583039.0f;   // M + 127
    const float CB_NEG = 12583040.0f;   // M + 128

    unsigned long long ivp[NP], app[NP];
    #pragma unroll
    for (int j = 0; j < NP; j++) {
        float a = invs[base + 2 * j], b = invs[base + 2 * j + 1];
        asm("mov.b64 %0, {%1,%2};" : "=l"(ivp[j]) : "f"(a), "f"(b));
        app[j] = 0ULL;
    }

    #pragma unroll 2
    for (int k = 0; k < EPT; k++) {
        float xv = row_sm[l64 + (k << 6)];
        float ax = fabsf(xv);
        float cb = (xv < 0.0f) ? CB_NEG : CB_POS;
        unsigned long long aa;
        asm("mov.b64 %0, {%1,%1};" : "=l"(aa) : "f"(ax));
        #pragma unroll
        for (int j = 0; j < NP; j++) {
            asm("{\n\t"
                ".reg .f32 n0,n1;\n\t"
                ".reg .b64 rr,nq,dd;\n\t"
                "fma.rn.f32x2 rr, %1, %2, %3;\n\t"   // M + round(u)
                "mov.b64 {n0,n1}, rr;\n\t"
                "min.f32 n0, n0, %4;\n\t"            // clamp to M+cb
                "min.f32 n1, n1, %4;\n\t"
                "mov.b64 rr, {n0,n1};\n\t"
                "sub.rn.f32x2 nq, %3, rr;\n\t"       // -q  (exact, rt=2)
                "fma.rn.f32x2 dd, %1, %2, nq;\n\t"   // u - q
                "fma.rn.f32x2 %0, dd, dd, %0;\n\t"   // acc += d*d
                "}"
                : "+l"(app[j])
                : "l"(aa), "l"(ivp[j]), "l"(M2), "f"(cb));
        }
    }

    #pragma unroll
    for (int j = 0; j < NP; j++) {
        float a0, a1;
        asm("mov.b64 {%0,%1}, %2;" : "=f"(a0), "=f"(a1) : "l"(app[j]));
        a0 = shfl_add(a0);
        a1 = shfl_add(a1);
        if (lane == 0) { partial[warp][2 * j] = a0; partial[warp][2 * j + 1] = a1; }
    }
}

__global__ __launch_bounds__(THREADS)
void mse_observer_kernel(const float* __restrict__ x, float* __restrict__ out,
                         unsigned long long M2) {
    __shared__ float row_sm[N_COLS];
    __shared__ float invs[N_STEPS];          // 1/scale_i
    __shared__ float s2k[N_STEPS];           // scale_i^2 / 8192
    __shared__ float thr_sm[N_STEPS];        // thres_i
    __shared__ float partial[8][2 * MAXP];   // per-warp partial sums (local idx)
    __shared__ float red_min[8], red_max[8];
    __shared__ float losses[N_STEPS];
    __shared__ float Rsh, rmin_sh, rmax_sh;

    const int row  = blockIdx.x;
    const int tid  = threadIdx.x;
    const int warp = tid >> 5;
    const int lane = tid & 31;
    const float* xr = x + (size_t)row * N_COLS;

    // ---- Phase A: load row to smem, compute row min/max ----
    float mn = 3.0e38f, mx = -3.0e38f;
    const float4* xr4 = (const float4*)xr;
    float4* row4 = (float4*)row_sm;
    #pragma unroll
    for (int k = 0; k < N_COLS / 4 / THREADS; k++) {   // 8 iterations
        float4 v = xr4[tid + k * THREADS];
        row4[tid + k * THREADS] = v;
        mn = fminf(mn, fminf(fminf(v.x, v.y), fminf(v.z, v.w)));
        mx = fmaxf(mx, fmaxf(fmaxf(v.x, v.y), fmaxf(v.z, v.w)));
    }
    #pragma unroll
    for (int o = 16; o; o >>= 1) {
        mn = fminf(mn, __shfl_xor_sync(0xFFFFFFFFu, mn, o));
        mx = fmaxf(mx, __shfl_xor_sync(0xFFFFFFFFu, mx, o));
    }
    if (lane == 0) { red_min[warp] = mn; red_max[warp] = mx; }
    __syncthreads();
    if (tid == 0) {
        float m = red_min[0], M = red_max[0];
        #pragma unroll
        for (int w = 1; w < 8; w++) { m = fminf(m, red_min[w]); M = fmaxf(M, red_max[w]); }
        rmin_sh = m; rmax_sh = M;
        Rsh = fmaxf(fabsf(m), M);   // range_val = max(|min|, max)
    }
    __syncthreads();

    // ---- Phase B: per-step tables ----
    if (tid < N_STEPS) {
        float R = Rsh;
        float thres = __fdiv_rn(R, 100.0f) * (float)(tid + 1);
        float scale = fmaxf(__fdiv_rn(thres, 127.5f), 1.1920928955078125e-07f);
        thr_sm[tid] = thres;
        invs[tid]   = __fdiv_rn(1.0f, scale);
        s2k[tid]    = scale * scale * (1.0f / 8192.0f);
    }
    __syncthreads();

    // ---- Phase C: groups 0,1 -> 12 pairs (steps 0..23, 24..47);
    //               groups 2,3 -> 13 pairs (steps 48..73, 74..99)
    const int grp = tid >> 6;
    const int l64 = tid & 63;
    if (grp == 0)      run_group<12>(row_sm, invs, partial,  0, l64, warp, lane, M2);
    else if (grp == 1) run_group<12>(row_sm, invs, partial, 24, l64, warp, lane, M2);
    else if (grp == 2) run_group<13>(row_sm, invs, partial, 48, l64, warp, lane, M2);
    else               run_group<13>(row_sm, invs, partial, 74, l64, warp, lane, M2);
    __syncthreads();

    // ---- Phase D: combine warp pairs into losses ----
    if (tid < N_STEPS) {
        int s = tid;
        int g, jj;
        if (s < 48) { g = s / 24; jj = s - 24 * g; }
        else        { g = 2 + (s - 48) / 26; jj = (s - 48) % 26; }
        float sum = partial[2 * g][jj] + partial[2 * g + 1][jj];
        losses[s] = sum * s2k[s];   // mean((xq-x)^2)
    }
    __syncthreads();

    // ---- Phase E: sequential argmin scan (matches lax.scan semantics) ----
    if (tid == 0) {
        float best = 1.0e9f;
        float bmin = rmin_sh, bmax = rmax_sh;
        for (int j = 0; j < N_STEPS; j++) {
            float L = losses[j];
            if (L < best) { best = L; bmin = -thr_sm[j]; bmax = thr_sm[j]; }
        }
        out[row] = bmin;
        out[N_ROWS + row] = bmax;
    }
}

extern "C" void kernel_launch(void* const* d_in, const int* in_sizes, int n_in,
                              void* d_out, int out_size) {
    const float* x = (const float*)d_in[0];
    float* out = (float*)d_out;
    // MAGIC2 = {1.5*2^23, 1.5*2^23} passed as a param so ptxas keeps it in a
    // uniform register (no RF-bank cost on the fma.f32x2 sources).
    mse_observer_kernel<<<N_ROWS, THREADS>>>(x, out, 0x4B4000004B400000ULL);
}